// round 17
// baseline (speedup 1.0000x reference)
#include <cuda_runtime.h>
#include <cuda_bf16.h>
#include <cstddef>
#include <cstdint>

#define B_DIM 256
#define D_DIM 4096
#define D4    (4 * D_DIM)

typedef unsigned long long ull;

// ---------------- scratch (static __device__ globals; no allocation) --------
__device__ float g_part    [2 * B_DIM * D4];   // 33.5 MB split-K partials (max: W2)
__device__ float g_recurrent[B_DIM * D_DIM];   // 4 MB
__device__ float g_asm_act [B_DIM * D_DIM];    // 4 MB
__device__ float g_asm_rec [B_DIM * D_DIM];    // 4 MB
__device__ float g_mod     [B_DIM * D_DIM];    // 4 MB
__device__ float g_hidden  [B_DIM * D_DIM];    // 4 MB
__device__ float g_statsW  [2 * D_DIM];        // rowmax, rowsumexp
__device__ float g_statsRW [2 * D_DIM];

// ---------------- packed fp32x2 helpers (lane-wise IEEE RN fp32 FMA) --------
__device__ __forceinline__ ull pack2dup(float x) {
    ull r; asm("mov.b64 %0, {%1, %1};" : "=l"(r) : "f"(x)); return r;
}
__device__ __forceinline__ void fma2(ull& d, ull a, ull b) {
    asm("fma.rn.f32x2 %0, %1, %2, %0;" : "+l"(d) : "l"(a), "l"(b));
}

__device__ __forceinline__ uint32_t cvta_smem(const void* p) {
    uint32_t a;
    asm("{ .reg .u64 t; cvta.to.shared.u64 t, %1; cvt.u32.u64 %0, t; }"
        : "=r"(a) : "l"(p));
    return a;
}

// ============================================================================
// Forward GEMM — bit-exact split-K=2 slabs, FFMA2, 8x8 thread tile.
// 128 threads/CTA, CTA tile 64x128, BK=16. grid = (N/128, M/64, 2).
// Per output element: pure ascending-k fp32 FMA chain over this z-slab.
// LDS per k per thread: 2xLDS.128 (a) + 2xLDS.128 (b) = 64B for 32 FFMA2.
// ============================================================================
__global__ void __launch_bounds__(128, 3)
fwd_gemm_kernel(const float* __restrict__ A, const float* __restrict__ Bm,
                float* __restrict__ P, int M, int N, int K)
{
    constexpr int BM = 64, BN = 128, BK = 16;
    __shared__ __align__(16) float As[2][BK][BM];
    __shared__ __align__(16) float Bs[2][BK][BN];

    const int tid = threadIdx.x;          // 128 threads
    const int tx  = tid & 15;             // 16 col groups of 8
    const int ty  = tid >> 4;             // 8 row groups of 8
    const int n0  = blockIdx.x * BN;
    const int m0  = blockIdx.y * BM;
    const int kh  = K >> 1;
    const int kbeg   = blockIdx.z * kh;
    const int ktiles = kh / BK;

    // loaders (128 threads)
    const int a_r = tid >> 1;             // 0..63 (row in A tile)
    const int a_c = (tid & 1) * 8;        // k offset {0,8}: 2 float4
    const int b_r = tid >> 3;             // 0..15 (k row in B tile)
    const int b_c = (tid & 7) * 16;       // 16 consecutive cols: 4 float4

    const float* Aptr = A + (size_t)(m0 + a_r) * K + kbeg + a_c;
    const float* Bptr = Bm + (size_t)(kbeg + b_r) * N + n0 + b_c;

    ull acc[8][4];                        // 8 rows x 4 col-pairs (8 cols)
#pragma unroll
    for (int i = 0; i < 8; i++)
#pragma unroll
        for (int j = 0; j < 4; j++) acc[i][j] = 0ull;

    float4 av0, av1, bv0, bv1, bv2, bv3;

    // preload tile 0
    av0 = *(const float4*)Aptr;
    av1 = *(const float4*)(Aptr + 4);
    bv0 = *(const float4*)Bptr;
    bv1 = *(const float4*)(Bptr + 4);
    bv2 = *(const float4*)(Bptr + 8);
    bv3 = *(const float4*)(Bptr + 12);
    {
        float tmp[8] = {av0.x, av0.y, av0.z, av0.w, av1.x, av1.y, av1.z, av1.w};
#pragma unroll
        for (int q = 0; q < 8; q++) As[0][a_c + q][a_r] = tmp[q];
        *(float4*)&Bs[0][b_r][b_c]      = bv0;
        *(float4*)&Bs[0][b_r][b_c + 4]  = bv1;
        *(float4*)&Bs[0][b_r][b_c + 8]  = bv2;
        *(float4*)&Bs[0][b_r][b_c + 12] = bv3;
    }
    __syncthreads();

    int buf = 0;
    for (int t = 0; t < ktiles; ++t) {
        if (t + 1 < ktiles) {
            const float* nA = Aptr + (t + 1) * BK;
            const float* nB = Bptr + (size_t)(t + 1) * BK * N;
            av0 = *(const float4*)nA;
            av1 = *(const float4*)(nA + 4);
            bv0 = *(const float4*)nB;
            bv1 = *(const float4*)(nB + 4);
            bv2 = *(const float4*)(nB + 8);
            bv3 = *(const float4*)(nB + 12);
        }
#pragma unroll
        for (int k = 0; k < BK; k++) {
            float a8[8];
            *(float4*)&a8[0] = *(const float4*)&As[buf][k][ty * 8];
            *(float4*)&a8[4] = *(const float4*)&As[buf][k][ty * 8 + 4];
            ull b[4];
            *(float4*)&b[0] = *(const float4*)&Bs[buf][k][tx * 8];      // b0,b1
            *(float4*)&b[2] = *(const float4*)&Bs[buf][k][tx * 8 + 4];  // b2,b3
#pragma unroll
            for (int i = 0; i < 8; i++) {
                const ull a2 = pack2dup(a8[i]);
                fma2(acc[i][0], a2, b[0]);
                fma2(acc[i][1], a2, b[1]);
                fma2(acc[i][2], a2, b[2]);
                fma2(acc[i][3], a2, b[3]);
            }
        }
        if (t + 1 < ktiles) {
            const int nb = buf ^ 1;
            float tmp[8] = {av0.x, av0.y, av0.z, av0.w, av1.x, av1.y, av1.z, av1.w};
#pragma unroll
            for (int q = 0; q < 8; q++) As[nb][a_c + q][a_r] = tmp[q];
            *(float4*)&Bs[nb][b_r][b_c]      = bv0;
            *(float4*)&Bs[nb][b_r][b_c + 4]  = bv1;
            *(float4*)&Bs[nb][b_r][b_c + 8]  = bv2;
            *(float4*)&Bs[nb][b_r][b_c + 12] = bv3;
            __syncthreads();
        }
        buf ^= 1;
    }

    // write partial slab
    float* Pz = P + (size_t)blockIdx.z * M * N;
    const int rA = m0 + ty * 8;
    const int cA = n0 + tx * 8;
#pragma unroll
    for (int i = 0; i < 8; i++) {
        const size_t off = (size_t)(rA + i) * N + cA;
        *(float4*)&Pz[off]     = *(float4*)&acc[i][0];
        *(float4*)&Pz[off + 4] = *(float4*)&acc[i][2];
    }
}

// ============================================================================
// Hebbian GEMM via bf16 mma.sync (HMMA) + fused epilogue (unchanged R16).
// ============================================================================
__device__ __forceinline__ uint32_t hswz(uint32_t k, uint32_t c) {
    return k * 256u + ((((c >> 3) ^ (k & 7)) << 4) | ((c & 7) << 1));
}

__device__ __forceinline__ void sts_bf16x8(uint32_t addr, float4 v0, float4 v1) {
    __nv_bfloat162 p0 = __floats2bfloat162_rn(v0.x, v0.y);
    __nv_bfloat162 p1 = __floats2bfloat162_rn(v0.z, v0.w);
    __nv_bfloat162 p2 = __floats2bfloat162_rn(v1.x, v1.y);
    __nv_bfloat162 p3 = __floats2bfloat162_rn(v1.z, v1.w);
    uint32_t u0 = *(uint32_t*)&p0, u1 = *(uint32_t*)&p1;
    uint32_t u2 = *(uint32_t*)&p2, u3 = *(uint32_t*)&p3;
    asm volatile("st.shared.v4.b32 [%0], {%1,%2,%3,%4};"
                 :: "r"(addr), "r"(u0), "r"(u1), "r"(u2), "r"(u3) : "memory");
}

__device__ __forceinline__ void ldsm4t(uint32_t* r, uint32_t addr) {
    asm volatile("ldmatrix.sync.aligned.m8n8.x4.trans.shared.b16 {%0,%1,%2,%3}, [%4];"
                 : "=r"(r[0]), "=r"(r[1]), "=r"(r[2]), "=r"(r[3]) : "r"(addr));
}

__device__ __forceinline__ void mma_bf16(float* c, const uint32_t* a,
                                         uint32_t b0, uint32_t b1) {
    asm volatile(
        "mma.sync.aligned.m16n8k16.row.col.f32.bf16.bf16.f32 "
        "{%0,%1,%2,%3}, {%4,%5,%6,%7}, {%8,%9}, {%0,%1,%2,%3};"
        : "+f"(c[0]), "+f"(c[1]), "+f"(c[2]), "+f"(c[3])
        : "r"(a[0]), "r"(a[1]), "r"(a[2]), "r"(a[3]), "r"(b0), "r"(b1));
}

__global__ void __launch_bounds__(256)
hebb_mma_kernel(const float* __restrict__ Am, const float* __restrict__ Bm,
                const float* __restrict__ Wmat, const float* __restrict__ stats,
                const float* __restrict__ decay, float* __restrict__ out)
{
    __shared__ __align__(16) unsigned char sA[2][4096];
    __shared__ __align__(16) unsigned char sB[2][4096];
    const int tid  = threadIdx.x;
    const int lane = tid & 31;
    const int wid  = tid >> 5;
    const int mw   = wid >> 2;
    const int nw   = wid & 3;
    const uint32_t sAb = cvta_smem(sA);
    const uint32_t sBb = cvta_smem(sB);

    const int lr = tid >> 4;
    const int lc = (tid & 15) * 8;
    const float* gA = Am + (size_t)lr * D_DIM + blockIdx.y * 128 + lc;
    const float* gB = Bm + (size_t)lr * D_DIM + blockIdx.x * 128 + lc;
    const uint32_t stOff = hswz((uint32_t)lr, (uint32_t)lc);

    const uint32_t arow  = ((lane >> 4) & 1) * 8 + (lane & 7);
    const uint32_t acolH = ((lane >> 3) & 1) * 8;
    uint32_t aOff[4];
#pragma unroll
    for (int mi = 0; mi < 4; mi++)
        aOff[mi] = hswz(arow, mw * 64 + mi * 16 + acolH);
    const uint32_t brow  = ((lane >> 3) & 1) * 8 + (lane & 7);
    const uint32_t bcolH = ((lane >> 4) & 1) * 8;
    uint32_t bOff[2];
#pragma unroll
    for (int nb = 0; nb < 2; nb++)
        bOff[nb] = hswz(brow, nw * 32 + nb * 16 + bcolH);

    float c[4][4][4];
#pragma unroll
    for (int mi = 0; mi < 4; mi++)
#pragma unroll
        for (int ni = 0; ni < 4; ni++)
#pragma unroll
            for (int q = 0; q < 4; q++) c[mi][ni][q] = 0.f;

    {
        float4 a0 = *(const float4*)gA;
        float4 a1 = *(const float4*)(gA + 4);
        float4 b0 = *(const float4*)gB;
        float4 b1 = *(const float4*)(gB + 4);
        sts_bf16x8(sAb + stOff, a0, a1);
        sts_bf16x8(sBb + stOff, b0, b1);
    }
    __syncthreads();

    for (int t = 0; t < 16; t++) {
        const uint32_t tb = (uint32_t)(t & 1) * 4096u;
        float4 pa0, pa1, pb0, pb1;
        if (t < 15) {
            const float* nA = gA + (size_t)(t + 1) * 16 * D_DIM;
            const float* nB = gB + (size_t)(t + 1) * 16 * D_DIM;
            pa0 = *(const float4*)nA;  pa1 = *(const float4*)(nA + 4);
            pb0 = *(const float4*)nB;  pb1 = *(const float4*)(nB + 4);
        }
        uint32_t af[4][4], bf[2][4];
#pragma unroll
        for (int mi = 0; mi < 4; mi++) ldsm4t(af[mi], sAb + tb + aOff[mi]);
#pragma unroll
        for (int nb = 0; nb < 2; nb++) ldsm4t(bf[nb], sBb + tb + bOff[nb]);
#pragma unroll
        for (int mi = 0; mi < 4; mi++)
#pragma unroll
            for (int ni = 0; ni < 4; ni++)
                mma_bf16(c[mi][ni], af[mi],
                         bf[ni >> 1][(ni & 1) * 2], bf[ni >> 1][(ni & 1) * 2 + 1]);
        if (t < 15) {
            const uint32_t nbuf = (uint32_t)((t + 1) & 1) * 4096u;
            sts_bf16x8(sAb + nbuf + stOff, pa0, pa1);
            sts_bf16x8(sBb + nbuf + stOff, pb0, pb1);
        }
        __syncthreads();
    }

    const int rbase = blockIdx.y * 128 + mw * 64 + (lane >> 2);
    const int cbase = blockIdx.x * 128 + nw * 32 + 2 * (lane & 3);
#pragma unroll
    for (int mi = 0; mi < 4; mi++) {
#pragma unroll
        for (int half = 0; half < 2; half++) {
            const int r = rbase + mi * 16 + half * 8;
            const float mx  = stats[r];
            const float sum = stats[D_DIM + r];
            const float dec = decay[r];
#pragma unroll
            for (int ni = 0; ni < 4; ni++) {
                const int cc = cbase + ni * 8;
                const size_t idx = (size_t)r * D_DIM + cc;
                const float2 wp = *(const float2*)&Wmat[idx];
                const float v0 = c[mi][ni][half * 2 + 0];
                const float v1 = c[mi][ni][half * 2 + 1];
                float2 o;
                {
                    const float wsm = __fdiv_rn(expf(__fsub_rn(wp.x, mx)), sum);
                    const float Mv    = __fmul_rn(v0, 0.00390625f);
                    const float delta = __fmul_rn(wsm, Mv);
                    o.x = __fsub_rn(__fadd_rn(wp.x, delta), __fmul_rn(dec, wp.x));
                }
                {
                    const float wsm = __fdiv_rn(expf(__fsub_rn(wp.y, mx)), sum);
                    const float Mv    = __fmul_rn(v1, 0.00390625f);
                    const float delta = __fmul_rn(wsm, Mv);
                    o.y = __fsub_rn(__fadd_rn(wp.y, delta), __fmul_rn(dec, wp.y));
                }
                *(float2*)&out[idx] = o;
            }
        }
    }
}

// ============================================================================
// Combine kernels (ordered __fadd_rn slab folds + epilogues)
// ============================================================================
// Fused: rec = p1a+p1b (store); acts = relu(relu(p2a+p2b+rec)-thr) (store)
__global__ void combine_rec_acts_kernel(const float* __restrict__ P1,
                                        const float* __restrict__ P2,
                                        const float* __restrict__ gab,
                                        const float* __restrict__ glu,
                                        float* __restrict__ rec_out,
                                        float* __restrict__ acts_out, int n)
{
    const int i = (blockIdx.x * blockDim.x + threadIdx.x) * 4;
    const float4 q0 = *(const float4*)&P1[i];
    const float4 q1 = *(const float4*)&P1[n + i];
    const float4 p0 = *(const float4*)&P2[i];
    const float4 p1 = *(const float4*)&P2[n + i];
    const float4 gb = *(const float4*)&gab[i];
    const float4 gl = *(const float4*)&glu[i];
    float rec[4] = {__fadd_rn(q0.x, q1.x), __fadd_rn(q0.y, q1.y),
                    __fadd_rn(q0.z, q1.z), __fadd_rn(q0.w, q1.w)};
    float tot[4] = {__fadd_rn(p0.x, p1.x), __fadd_rn(p0.y, p1.y),
                    __fadd_rn(p0.z, p1.z), __fadd_rn(p0.w, p1.w)};
    const float gbv[4] = {gb.x, gb.y, gb.z, gb.w};
    const float glv[4] = {gl.x, gl.y, gl.z, gl.w};
    float o[4];
#pragma unroll
    for (int q = 0; q < 4; q++) {
        float v = __fadd_rn(tot[q], rec[q]);
        v = fmaxf(v, 0.f);
        const float t1  = __fsub_rn(1.0f, gbv[q]);
        const float t2  = __fadd_rn(t1, glv[q]);
        const float thr = __fmul_rn(0.5f, t2);
        o[q] = fmaxf(__fsub_rn(v, thr), 0.f);
    }
    *(float4*)&rec_out[i]  = make_float4(rec[0], rec[1], rec[2], rec[3]);
    *(float4*)&acts_out[i] = make_float4(o[0], o[1], o[2], o[3]);
}

__global__ void combine_biasrelu_kernel(const float* __restrict__ P,
                                        const float* __restrict__ b1,
                                        float* __restrict__ out, int n)
{
    const int i = (blockIdx.x * blockDim.x + threadIdx.x) * 4;
    const float4 p0 = *(const float4*)&P[i];
    const float4 p1 = *(const float4*)&P[n + i];
    const float4 bb = *(const float4*)&b1[i & (D_DIM - 1)];
    float4 r;
    r.x = fmaxf(__fadd_rn(__fadd_rn(p0.x, p1.x), bb.x), 0.f);
    r.y = fmaxf(__fadd_rn(__fadd_rn(p0.y, p1.y), bb.y), 0.f);
    r.z = fmaxf(__fadd_rn(__fadd_rn(p0.z, p1.z), bb.z), 0.f);
    r.w = fmaxf(__fadd_rn(__fadd_rn(p0.w, p1.w), bb.w), 0.f);
    *(float4*)&out[i] = r;
}

__global__ void combine_neuro_kernel(const float* __restrict__ P,
                                     const float* __restrict__ b2,
                                     const float* __restrict__ dop,
                                     const float* __restrict__ ser,
                                     const float* __restrict__ glu,
                                     const float* __restrict__ gab,
                                     float* __restrict__ out)
{
    const int gid = blockIdx.x * blockDim.x + threadIdx.x;
    const int r = gid >> 12;
    const int d = gid & (D_DIM - 1);
    const size_t base = (size_t)r * D4 + d * 4;
    const float4 p0 = *(const float4*)&P[base];
    const float4 p1 = *(const float4*)&P[(size_t)B_DIM * D4 + base];
    const float4 bb = *(const float4*)&b2[d * 4];
    float t[4];
    t[0] = tanhf(__fadd_rn(__fadd_rn(p0.x, p1.x), bb.x));
    t[1] = tanhf(__fadd_rn(__fadd_rn(p0.y, p1.y), bb.y));
    t[2] = tanhf(__fadd_rn(__fadd_rn(p0.z, p1.z), bb.z));
    t[3] = tanhf(__fadd_rn(__fadd_rn(p0.w, p1.w), bb.w));
    const float inv = __fdiv_rn(1.0f, fmaxf(fabsf(t[1]), 1e-6f));
    const size_t src = (size_t)r * D_DIM + d;
    out[(size_t)(1 * B_DIM + r) * D_DIM + d] = __fadd_rn(dop[src], __fmul_rn(t[0], inv));
    out[(size_t)(2 * B_DIM + r) * D_DIM + d] = __fadd_rn(ser[src], t[1]);
    out[(size_t)(3 * B_DIM + r) * D_DIM + d] = __fadd_rn(glu[src], __fmul_rn(t[2], inv));
    out[(size_t)(4 * B_DIM + r) * D_DIM + d] = __fadd_rn(gab[src], __fmul_rn(t[3], inv));
}

// ------------- row softmax over [rows, 4096], one block per row -------------
__global__ void softmax_rows_kernel(const float* __restrict__ in,
                                    float* __restrict__ out)
{
    const int row = blockIdx.x;
    const int t   = threadIdx.x;
    const float* x = in + (size_t)row * D_DIM;
    float v[16];
    float mx = -3.402823e38f;
#pragma unroll
    for (int i = 0; i < 16; i++) { v[i] = x[t + i * 256]; mx = fmaxf(mx, v[i]); }

    __shared__ float red[256];
    red[t] = mx; __syncthreads();
    for (int s = 128; s > 0; s >>= 1) {
        if (t < s) red[t] = fmaxf(red[t], red[t + s]);
        __syncthreads();
    }
    const float m = red[0]; __syncthreads();

    float s = 0.f;
#pragma unroll
    for (int i = 0; i < 16; i++) { v[i] = expf(__fsub_rn(v[i], m)); s = __fadd_rn(s, v[i]); }
    red[t] = s; __syncthreads();
    for (int st = 128; st > 0; st >>= 1) {
        if (t < st) red[t] = __fadd_rn(red[t], red[t + st]);
        __syncthreads();
    }
    const float den = red[0];
#pragma unroll
    for (int i = 0; i < 16; i++)
        out[(size_t)row * D_DIM + t + i * 256] = __fdiv_rn(v[i], den);
}

// ------------- per-row max & sum(exp(x-max)) for a [4096,4096] matrix -------
__global__ void rowstats_kernel(const float* __restrict__ in,
                                float* __restrict__ stats)
{
    const int row = blockIdx.x;
    const int t   = threadIdx.x;
    const float* x = in + (size_t)row * D_DIM;
    float v[16];
    float mx = -3.402823e38f;
#pragma unroll
    for (int i = 0; i < 16; i++) { v[i] = x[t + i * 256]; mx = fmaxf(mx, v[i]); }

    __shared__ float red[256];
    red[t] = mx; __syncthreads();
    for (int s = 128; s > 0; s >>= 1) {
        if (t < s) red[t] = fmaxf(red[t], red[t + s]);
        __syncthreads();
    }
    const float m = red[0]; __syncthreads();

    float s = 0.f;
#pragma unroll
    for (int i = 0; i < 16; i++) s = __fadd_rn(s, expf(__fsub_rn(v[i], m)));
    red[t] = s; __syncthreads();
    for (int st = 128; st > 0; st >>= 1) {
        if (t < st) red[t] = __fadd_rn(red[t], red[t + st]);
        __syncthreads();
    }
    if (t == 0) { stats[row] = m; stats[D_DIM + row] = red[0]; }
}

// ------------- mod = (alpha[j] * dopamine) * serotonin ----------------------
__global__ void mod_kernel(const float* __restrict__ alpha,
                           const float* __restrict__ dop,
                           const float* __restrict__ ser,
                           float* __restrict__ out)
{
    const int i = blockIdx.x * blockDim.x + threadIdx.x;
    const int j = i & (D_DIM - 1);
    out[i] = __fmul_rn(__fmul_rn(alpha[j], dop[i]), ser[i]);
}

// ----------------------------------------------------------------------------
extern "C" void kernel_launch(void* const* d_in, const int* in_sizes, int n_in,
                              void* d_out, int out_size)
{
    const float* x      = (const float*)d_in[0];
    const float* W      = (const float*)d_in[1];
    const float* RW     = (const float*)d_in[2];
    const float* alpha  = (const float*)d_in[3];
    const float* decay  = (const float*)d_in[4];
    const float* dop    = (const float*)d_in[5];
    const float* ser    = (const float*)d_in[6];
    const float* glu    = (const float*)d_in[7];
    const float* gab    = (const float*)d_in[8];
    const float* prev   = (const float*)d_in[9];
    const float* W1     = (const float*)d_in[10];
    const float* b1     = (const float*)d_in[11];
    const float* W2     = (const float*)d_in[12];
    const float* b2     = (const float*)d_in[13];
    float* out = (float*)d_out;

    float *p_part, *p_rec, *p_asm_a, *p_asm_r, *p_mod, *p_hid, *p_stW, *p_stRW;
    cudaGetSymbolAddress((void**)&p_part,  g_part);
    cudaGetSymbolAddress((void**)&p_rec,   g_recurrent);
    cudaGetSymbolAddress((void**)&p_asm_a, g_asm_act);
    cudaGetSymbolAddress((void**)&p_asm_r, g_asm_rec);
    cudaGetSymbolAddress((void**)&p_mod,   g_mod);
    cudaGetSymbolAddress((void**)&p_hid,   g_hidden);
    cudaGetSymbolAddress((void**)&p_stW,   g_statsW);
    cudaGetSymbolAddress((void**)&p_stRW,  g_statsRW);

    float* acts_out  = out;
    float* Wnew_out  = out + (size_t)5 * B_DIM * D_DIM;
    float* RWnew_out = Wnew_out + (size_t)D_DIM * D_DIM;

    const dim3 blk(256);
    const dim3 blk_g(128);
    const dim3 grid_fwd(D_DIM / 128, B_DIM / 64, 2);
    const dim3 grid_w2(D4 / 128, B_DIM / 64, 2);
    const dim3 grid_hebb(D_DIM / 128, D_DIM / 128);   // 32 x 32
    const int  nBD = B_DIM * D_DIM;
    const int  cmb_blocks = nBD / (256 * 4);

    // independent prep first
    mod_kernel<<<nBD / 256, blk>>>(alpha, dop, ser, p_mod);
    rowstats_kernel<<<D_DIM, blk>>>(W,  p_stW);
    rowstats_kernel<<<D_DIM, blk>>>(RW, p_stRW);

    // GEMM1: recurrent partials; GEMM2: x@W partials (separate buffer region)
    fwd_gemm_kernel<<<grid_fwd, blk_g>>>(prev, RW, p_part, B_DIM, D_DIM, D_DIM);
    fwd_gemm_kernel<<<grid_fwd, blk_g>>>(x, W, p_part + (size_t)2 * nBD,
                                         B_DIM, D_DIM, D_DIM);
    // fused combine: rec + acts
    combine_rec_acts_kernel<<<cmb_blocks, blk>>>(p_part, p_part + (size_t)2 * nBD,
                                                 gab, glu, p_rec, acts_out, nBD);

    // row softmax of acts and recurrent
    softmax_rows_kernel<<<B_DIM, blk>>>(acts_out, p_asm_a);
    softmax_rows_kernel<<<B_DIM, blk>>>(p_rec, p_asm_r);

    // Hebbian updates — bf16 tensor-core GEMMs with fused epilogue
    hebb_mma_kernel<<<grid_hebb, blk>>>(p_asm_a, p_mod, W,  p_stW,  decay, Wnew_out);
    hebb_mma_kernel<<<grid_hebb, blk>>>(p_asm_r, p_mod, RW, p_stRW, decay, RWnew_out);

    // hidden = relu(acts @ W1 + b1)
    fwd_gemm_kernel<<<grid_fwd, blk_g>>>(acts_out, W1, p_part, B_DIM, D_DIM, D_DIM);
    combine_biasrelu_kernel<<<cmb_blocks, blk>>>(p_part, b1, p_hid, nBD);

    // h = tanh(hidden @ W2 + b2) -> neuromodulator scatter
    fwd_gemm_kernel<<<grid_w2, blk_g>>>(p_hid, W2, p_part, B_DIM, D4, D_DIM);
    combine_neuro_kernel<<<nBD / 256, blk>>>(p_part, b2, dop, ser, glu, gab, out);
}